// round 5
// baseline (speedup 1.0000x reference)
#include <cuda_runtime.h>

// Problem: B=2, 128^3 grid, C=3, 7 scaling-and-squaring steps.
#define D 128
#define DMASK 127
#define D3 (D * D * D)          // 2097152
#define NVOX (2 * D3)           // 4194304 voxels (B=2)
#define NTHREADS 256
#define NBLOCKS (NVOX / NTHREADS)

// Ping-pong buffers: one float4 (x,y,z,pad) per voxel, 64 MB each.
// Layout: [b*D3 + x*D*D + y*D + z].
__device__ float4 gA4[NVOX];
__device__ float4 gB4[NVOX];

// ---------------------------------------------------------------------------
// Pack + scale: AoS float3 dvf -> float4 (x,y,z,0) * 2^-7 in gA4.
// ---------------------------------------------------------------------------
__global__ __launch_bounds__(NTHREADS) void pack_scale_kernel(
    const float* __restrict__ in)
{
    const int idx = blockIdx.x * NTHREADS + threadIdx.x;   // voxel id
    const float s = 1.0f / 128.0f;                         // 2^-7, exact
    const float* p = in + 3 * idx;
    gA4[idx] = make_float4(s * p[0], s * p[1], s * p[2], 0.0f);
}

// ---------------------------------------------------------------------------
// One squaring step. SRC: 1 = gA4, 2 = gB4.  DST: 0 = AoS d_out, 1/2 = gA4/gB4.
// One LDG.128 per trilinear corner (all 3 components at once).
// ---------------------------------------------------------------------------
template <int SRC, int DST>
__global__ __launch_bounds__(NTHREADS) void step_f4_kernel(
    float* __restrict__ ext_out)
{
    const float4* __restrict__ src = (SRC == 1) ? gA4 : gB4;

    const int idx = blockIdx.x * NTHREADS + threadIdx.x;

    const int z = idx & DMASK;
    const int y = (idx >> 7) & DMASK;
    const int x = (idx >> 14) & DMASK;
    const int bbase = (idx >> 21) * D3;

    // Center displacement (coalesced LDG.128).
    const float4 v = src[idx];

    const float lx = (float)x + v.x;
    const float ly = (float)y + v.y;
    const float lz = (float)z + v.z;

    const float fx = floorf(lx), fy = floorf(ly), fz = floorf(lz);
    const float wx1 = lx - fx, wy1 = ly - fy, wz1 = lz - fz;
    const float wx0 = 1.0f - wx1, wy0 = 1.0f - wy1, wz0 = 1.0f - wz1;

    const int ix = (int)fx, iy = (int)fy, iz = (int)fz;

    // Clip corner indices; weights stay unclipped (matches reference).
    const int ix0 = min(max(ix,     0), DMASK);
    const int ix1 = min(max(ix + 1, 0), DMASK);
    const int iy0 = min(max(iy,     0), DMASK);
    const int iy1 = min(max(iy + 1, 0), DMASK);
    const int iz0 = min(max(iz,     0), DMASK);
    const int iz1 = min(max(iz + 1, 0), DMASK);

    const int X0 = bbase + ix0 * (D * D);
    const int X1 = bbase + ix1 * (D * D);
    const int Y0 = iy0 * D;
    const int Y1 = iy1 * D;

    const float w00 = wx0 * wy0;
    const float w01 = wx0 * wy1;
    const float w10 = wx1 * wy0;
    const float w11 = wx1 * wy1;

    float ax = 0.0f, ay = 0.0f, az = 0.0f;

    #define CORNER(W, LIN)                                                    \
        do {                                                                  \
            const float  w_ = (W);                                            \
            const float4 c_ = __ldg(src + (LIN));                             \
            ax = fmaf(w_, c_.x, ax);                                          \
            ay = fmaf(w_, c_.y, ay);                                          \
            az = fmaf(w_, c_.z, az);                                          \
        } while (0)

    CORNER(w00 * wz0, X0 + Y0 + iz0);
    CORNER(w00 * wz1, X0 + Y0 + iz1);
    CORNER(w01 * wz0, X0 + Y1 + iz0);
    CORNER(w01 * wz1, X0 + Y1 + iz1);
    CORNER(w10 * wz0, X1 + Y0 + iz0);
    CORNER(w10 * wz1, X1 + Y0 + iz1);
    CORNER(w11 * wz0, X1 + Y1 + iz0);
    CORNER(w11 * wz1, X1 + Y1 + iz1);
    #undef CORNER

    const float ox = v.x + ax;
    const float oy = v.y + ay;
    const float oz = v.z + az;

    if (DST == 0) {
        // Final step: AoS float3 into d_out.
        float* o = ext_out + 3 * idx;
        o[0] = ox; o[1] = oy; o[2] = oz;
    } else {
        float4* dst = (DST == 1) ? gA4 : gB4;
        dst[idx] = make_float4(ox, oy, oz, 0.0f);
    }
}

extern "C" void kernel_launch(void* const* d_in, const int* in_sizes, int n_in,
                              void* d_out, int out_size)
{
    const float* dvf = (const float*)d_in[0];
    float* out = (float*)d_out;

    // AoS dvf -> scaled float4 field in gA4 (ddf0 = dvf * 2^-7, exact).
    pack_scale_kernel<<<NBLOCKS, NTHREADS>>>(dvf);

    // 7 squaring steps, ping-pong; final step writes AoS into d_out.
    step_f4_kernel<1, 2><<<NBLOCKS, NTHREADS>>>(nullptr);  // 1: A -> B
    step_f4_kernel<2, 1><<<NBLOCKS, NTHREADS>>>(nullptr);  // 2: B -> A
    step_f4_kernel<1, 2><<<NBLOCKS, NTHREADS>>>(nullptr);  // 3: A -> B
    step_f4_kernel<2, 1><<<NBLOCKS, NTHREADS>>>(nullptr);  // 4: B -> A
    step_f4_kernel<1, 2><<<NBLOCKS, NTHREADS>>>(nullptr);  // 5: A -> B
    step_f4_kernel<2, 1><<<NBLOCKS, NTHREADS>>>(nullptr);  // 6: B -> A
    step_f4_kernel<1, 0><<<NBLOCKS, NTHREADS>>>(out);      // 7: A -> d_out
}